// round 1
// baseline (speedup 1.0000x reference)
#include <cuda_runtime.h>
#include <cuda_bf16.h>

// GruDirection3d forward wavefront:
//   out[d,y,x] = z*h_tilde + (1-z)*out[d-1,y-1,x-1],  border -> h0
// One CTA per (b,c) volume. Sweep planes in d; previous output plane lives in
// a double-buffered 33x33 smem tile whose top row / left col stay h0 forever.
// Plane loads for d+1 are issued before the barrier (software pipeline).

#define DDIM 32
#define PLANE 1024     // 32*32
#define EXT 33

__global__ __launch_bounds__(1024, 1)
void gru3d_kernel(const float* __restrict__ z,
                  const float* __restrict__ ht,
                  const float* __restrict__ h0p,
                  float* __restrict__ out)
{
    __shared__ float buf[2][EXT * EXT];

    const float h0 = __ldg(h0p);
    const int tid = threadIdx.x;

    // Init both buffers (interior will be overwritten; border stays h0).
    #pragma unroll
    for (int i = tid; i < 2 * EXT * EXT; i += 1024)
        (&buf[0][0])[i] = h0;

    const int y = tid >> 5;
    const int x = tid & 31;

    const size_t base = (size_t)blockIdx.x * (DDIM * PLANE) + (size_t)(y * 32 + x);
    const float* zp = z  + base;
    const float* hp = ht + base;
    float*       op = out + base;

    // Prime the pipeline: load plane 0 before the first barrier.
    float zc = zp[0];
    float hc = hp[0];

    __syncthreads();   // buf init complete

    #pragma unroll
    for (int d = 0; d < DDIM; ++d) {
        // Prefetch next plane while this step's barrier/compute proceeds.
        float zn = 0.f, hn = 0.f;
        if (d < DDIM - 1) {
            zn = zp[(size_t)(d + 1) * PLANE];
            hn = hp[(size_t)(d + 1) * PLANE];
        }

        // prev = out[d-1, y-1, x-1]; ext coords [y][x] == logical (y-1,x-1),
        // with row 0 / col 0 of the ext tile pinned to h0.
        const float p = buf[(d + 1) & 1][y * EXT + x];

        // z*ht + (1-z)*p  ==  p + z*(ht - p)
        const float o = fmaf(zc, hc - p, p);

        buf[d & 1][(y + 1) * EXT + (x + 1)] = o;
        op[(size_t)d * PLANE] = o;

        __syncthreads();   // writes of step d visible before reads of step d+1

        zc = zn;
        hc = hn;
    }
}

extern "C" void kernel_launch(void* const* d_in, const int* in_sizes, int n_in,
                              void* d_out, int out_size)
{
    const float* z  = (const float*)d_in[0];
    const float* ht = (const float*)d_in[1];
    const float* h0 = (const float*)d_in[2];
    float* out = (float*)d_out;

    const int n_volumes = out_size / (DDIM * PLANE);   // B*C = 192
    gru3d_kernel<<<n_volumes, 1024>>>(z, ht, h0, out);
}